// round 1
// baseline (speedup 1.0000x reference)
#include <cuda_runtime.h>
#include <cstdint>

#define BATCH 8
#define HEADS 8
#define NSEQ  1024
#define CDIM  64

// ---------------- scratch (static device globals: no runtime allocation) ----------------
__device__ float g_q[BATCH*HEADS*NSEQ*CDIM];   // transformed, pre-scaled by 1/8
__device__ float g_k[BATCH*HEADS*NSEQ*CDIM];   // transformed with eta*inv*eta
__device__ float g_v[BATCH*HEADS*NSEQ*CDIM];   // transformed
__device__ float g_inv[BATCH*NSEQ*16];         // inv(frames) row-major

// ---------------- helpers ----------------
__device__ __forceinline__ uint32_t tf32bits(float x) {
  uint32_t r;
  asm("cvt.rna.tf32.f32 %0, %1;" : "=r"(r) : "f"(x));
  return r;
}
__device__ __forceinline__ float tf32f(float x) { return __uint_as_float(tf32bits(x)); }

__device__ __forceinline__ void mma_tf32(float* d, const uint32_t* a, uint32_t b0, uint32_t b1) {
  asm("mma.sync.aligned.m16n8k8.row.col.f32.tf32.tf32.f32 "
      "{%0,%1,%2,%3}, {%4,%5,%6,%7}, {%8,%9}, {%0,%1,%2,%3};\n"
      : "+f"(d[0]), "+f"(d[1]), "+f"(d[2]), "+f"(d[3])
      : "r"(a[0]), "r"(a[1]), "r"(a[2]), "r"(a[3]), "r"(b0), "r"(b1));
}

// ---------------- kernel 1: 4x4 inverses ----------------
__global__ void __launch_bounds__(256) invert_kernel(const float* __restrict__ frames) {
  int i = blockIdx.x * blockDim.x + threadIdx.x;
  if (i >= BATCH * NSEQ) return;
  const float* m = frames + (size_t)i * 16;
  float mm[16];
#pragma unroll
  for (int j = 0; j < 16; ++j) mm[j] = m[j];
  float inv[16];
  inv[0]  =  mm[5]*mm[10]*mm[15] - mm[5]*mm[11]*mm[14] - mm[9]*mm[6]*mm[15] + mm[9]*mm[7]*mm[14] + mm[13]*mm[6]*mm[11] - mm[13]*mm[7]*mm[10];
  inv[4]  = -mm[4]*mm[10]*mm[15] + mm[4]*mm[11]*mm[14] + mm[8]*mm[6]*mm[15] - mm[8]*mm[7]*mm[14] - mm[12]*mm[6]*mm[11] + mm[12]*mm[7]*mm[10];
  inv[8]  =  mm[4]*mm[9]*mm[15]  - mm[4]*mm[11]*mm[13] - mm[8]*mm[5]*mm[15] + mm[8]*mm[7]*mm[13] + mm[12]*mm[5]*mm[11] - mm[12]*mm[7]*mm[9];
  inv[12] = -mm[4]*mm[9]*mm[14]  + mm[4]*mm[10]*mm[13] + mm[8]*mm[5]*mm[14] - mm[8]*mm[6]*mm[13] - mm[12]*mm[5]*mm[10] + mm[12]*mm[6]*mm[9];
  inv[1]  = -mm[1]*mm[10]*mm[15] + mm[1]*mm[11]*mm[14] + mm[9]*mm[2]*mm[15] - mm[9]*mm[3]*mm[14] - mm[13]*mm[2]*mm[11] + mm[13]*mm[3]*mm[10];
  inv[5]  =  mm[0]*mm[10]*mm[15] - mm[0]*mm[11]*mm[14] - mm[8]*mm[2]*mm[15] + mm[8]*mm[3]*mm[14] + mm[12]*mm[2]*mm[11] - mm[12]*mm[3]*mm[10];
  inv[9]  = -mm[0]*mm[9]*mm[15]  + mm[0]*mm[11]*mm[13] + mm[8]*mm[1]*mm[15] - mm[8]*mm[3]*mm[13] - mm[12]*mm[1]*mm[11] + mm[12]*mm[3]*mm[9];
  inv[13] =  mm[0]*mm[9]*mm[14]  - mm[0]*mm[10]*mm[13] - mm[8]*mm[1]*mm[14] + mm[8]*mm[2]*mm[13] + mm[12]*mm[1]*mm[10] - mm[12]*mm[2]*mm[9];
  inv[2]  =  mm[1]*mm[6]*mm[15]  - mm[1]*mm[7]*mm[14]  - mm[5]*mm[2]*mm[15] + mm[5]*mm[3]*mm[14] + mm[13]*mm[2]*mm[7]  - mm[13]*mm[3]*mm[6];
  inv[6]  = -mm[0]*mm[6]*mm[15]  + mm[0]*mm[7]*mm[14]  + mm[4]*mm[2]*mm[15] - mm[4]*mm[3]*mm[14] - mm[12]*mm[2]*mm[7]  + mm[12]*mm[3]*mm[6];
  inv[10] =  mm[0]*mm[5]*mm[15]  - mm[0]*mm[7]*mm[13]  - mm[4]*mm[1]*mm[15] + mm[4]*mm[3]*mm[13] + mm[12]*mm[1]*mm[7]  - mm[12]*mm[3]*mm[5];
  inv[14] = -mm[0]*mm[5]*mm[14]  + mm[0]*mm[6]*mm[13]  + mm[4]*mm[1]*mm[14] - mm[4]*mm[2]*mm[13] - mm[12]*mm[1]*mm[6]  + mm[12]*mm[2]*mm[5];
  inv[3]  = -mm[1]*mm[6]*mm[11]  + mm[1]*mm[7]*mm[10]  + mm[5]*mm[2]*mm[11] - mm[5]*mm[3]*mm[10] - mm[9]*mm[2]*mm[7]   + mm[9]*mm[3]*mm[6];
  inv[7]  =  mm[0]*mm[6]*mm[11]  - mm[0]*mm[7]*mm[10]  - mm[4]*mm[2]*mm[11] + mm[4]*mm[3]*mm[10] + mm[8]*mm[2]*mm[7]   - mm[8]*mm[3]*mm[6];
  inv[11] = -mm[0]*mm[5]*mm[11]  + mm[0]*mm[7]*mm[9]   + mm[4]*mm[1]*mm[11] - mm[4]*mm[3]*mm[9]  - mm[8]*mm[1]*mm[7]   + mm[8]*mm[3]*mm[5];
  inv[15] =  mm[0]*mm[5]*mm[10]  - mm[0]*mm[6]*mm[9]   - mm[4]*mm[1]*mm[10] + mm[4]*mm[2]*mm[9]  + mm[8]*mm[1]*mm[6]   - mm[8]*mm[2]*mm[5];
  float det = mm[0]*inv[0] + mm[1]*inv[4] + mm[2]*inv[8] + mm[3]*inv[12];
  float id = 1.0f / det;
#pragma unroll
  for (int j = 0; j < 16; ++j) g_inv[(size_t)i * 16 + j] = inv[j] * id;
}

// ---------------- kernel 2: frame transform of q/k/v ----------------
// grid.x = BH*16 (64 rows per block), grid.y = 3 (q,k,v). 256 threads: 4 per row.
__global__ void __launch_bounds__(256) transform_kernel(
    const float* __restrict__ qin, const float* __restrict__ kin, const float* __restrict__ vin) {
  const int kind = blockIdx.y;
  const int bh   = blockIdx.x >> 4;
  const int nblk = blockIdx.x & 15;
  const int b    = bh >> 3;
  const int tid  = threadIdx.x;
  const int row  = tid >> 2;
  const int part = tid & 3;
  const int n0   = nblk * 64;

  __shared__ float Msm[64 * 16];
  const float* invp = g_inv + ((size_t)b * NSEQ + n0) * 16;
  for (int idx = tid; idx < 1024; idx += 256) Msm[idx] = invp[idx];
  __syncthreads();

  const float* x = (kind == 0 ? qin : kind == 1 ? kin : vin) + ((size_t)bh * NSEQ + n0) * CDIM;
  float*       y = (kind == 0 ? g_q : kind == 1 ? g_k : g_v) + ((size_t)bh * NSEQ + n0) * CDIM;
  const float scale = (kind == 0) ? 0.125f : 1.0f;   // fold 1/sqrt(C) into Q

  const float* xr = x + row * CDIM;
  float*       yr = y + row * CDIM;

  if (part == 0) {
#pragma unroll
    for (int c = 0; c < 16; c += 4) {
      float4 v = *reinterpret_cast<const float4*>(xr + c);
      v.x *= scale; v.y *= scale; v.z *= scale; v.w *= scale;
      *reinterpret_cast<float4*>(yr + c) = v;
    }
  } else {
    float M[16];
    const float* Mp = Msm + row * 16;
    if (kind == 1) {
#pragma unroll
      for (int i = 0; i < 4; ++i)
#pragma unroll
        for (int j = 0; j < 4; ++j) {
          float sgn = ((i == 0) == (j == 0)) ? 1.0f : -1.0f;  // eta*M*eta
          M[i * 4 + j] = Mp[i * 4 + j] * sgn;
        }
    } else {
#pragma unroll
      for (int i = 0; i < 16; ++i) M[i] = Mp[i] * scale;
    }
    const int base = 16 + (part - 1) * 16;
#pragma unroll
    for (int g = 0; g < 4; ++g) {
      float4 v = *reinterpret_cast<const float4*>(xr + base + g * 4);
      float4 o;
      o.x = M[0]*v.x  + M[1]*v.y  + M[2]*v.z  + M[3]*v.w;
      o.y = M[4]*v.x  + M[5]*v.y  + M[6]*v.z  + M[7]*v.w;
      o.z = M[8]*v.x  + M[9]*v.y  + M[10]*v.z + M[11]*v.w;
      o.w = M[12]*v.x + M[13]*v.y + M[14]*v.z + M[15]*v.w;
      *reinterpret_cast<float4*>(yr + base + g * 4) = o;
    }
  }
}

// ---------------- kernel 3: flash attention (tf32 mma) + fused output transform ----------------
// grid: (BH=64, 8 row-blocks of 128). 8 warps, 16 rows/warp. KV tile BN=32.
__global__ void __launch_bounds__(256) attn_kernel(const float* __restrict__ frames,
                                                   float* __restrict__ out) {
  __shared__ float sm[8704];   // K:[0,2176) V:[2176,4352) P:[4352,8576); epilogue reuses [0,8704)

  const int bh   = blockIdx.x;
  const int mb   = blockIdx.y;
  const int b    = bh >> 3;
  const int tid  = threadIdx.x;
  const int warp = tid >> 5;
  const int lane = tid & 31;
  const int qr   = lane >> 2;   // row within 8-row group
  const int t    = lane & 3;    // col group
  const int row0 = mb * 128 + warp * 16;

  const float* Qg = g_q + (size_t)bh * NSEQ * CDIM;
  const float* Kg = g_k + (size_t)bh * NSEQ * CDIM;
  const float* Vg = g_v + (size_t)bh * NSEQ * CDIM;

  // Q fragments (16 x 64), tf32
  uint32_t qa[8][4];
#pragma unroll
  for (int kk = 0; kk < 8; ++kk) {
    const float* q0 = Qg + (size_t)(row0 + qr)     * CDIM + kk * 8;
    const float* q1 = Qg + (size_t)(row0 + qr + 8) * CDIM + kk * 8;
    qa[kk][0] = tf32bits(q0[t]);
    qa[kk][1] = tf32bits(q1[t]);
    qa[kk][2] = tf32bits(q0[t + 4]);
    qa[kk][3] = tf32bits(q1[t + 4]);
  }

  float o[8][4];
#pragma unroll
  for (int j = 0; j < 8; ++j) { o[j][0]=0.f; o[j][1]=0.f; o[j][2]=0.f; o[j][3]=0.f; }
  float m0 = -1e30f, m1 = -1e30f, l0 = 0.f, l1 = 0.f;

  float* ksm = sm;                       // [32][68]
  float* vsm = sm + 2176;                // [32][68]
  float* psm = sm + 4352 + warp * 528;   // per-warp [16][33]

  for (int tile = 0; tile < NSEQ / 32; ++tile) {
    __syncthreads();
    const float4* Ksrc = reinterpret_cast<const float4*>(Kg + (size_t)tile * 32 * CDIM);
    const float4* Vsrc = reinterpret_cast<const float4*>(Vg + (size_t)tile * 32 * CDIM);
    for (int e = tid; e < 512; e += 256) {
      int r = e >> 4, c = (e & 15) << 2;
      float4 kf = Ksrc[e];
      float4 vf = Vsrc[e];
      float* kd = ksm + r * 68 + c;
      float* vd = vsm + r * 68 + c;
      kd[0] = tf32f(kf.x); kd[1] = tf32f(kf.y); kd[2] = tf32f(kf.z); kd[3] = tf32f(kf.w);
      vd[0] = tf32f(vf.x); vd[1] = tf32f(vf.y); vd[2] = tf32f(vf.z); vd[3] = tf32f(vf.w);
    }
    __syncthreads();

    // S = Q * K^T  (16 x 32)
    float s[4][4];
#pragma unroll
    for (int j = 0; j < 4; ++j) { s[j][0]=0.f; s[j][1]=0.f; s[j][2]=0.f; s[j][3]=0.f; }
#pragma unroll
    for (int kk = 0; kk < 8; ++kk) {
#pragma unroll
      for (int j = 0; j < 4; ++j) {
        uint32_t b0 = __float_as_uint(ksm[(j * 8 + qr) * 68 + kk * 8 + t]);
        uint32_t b1 = __float_as_uint(ksm[(j * 8 + qr) * 68 + kk * 8 + t + 4]);
        mma_tf32(s[j], qa[kk], b0, b1);
      }
    }

    // online softmax
    float mx0 = -1e30f, mx1 = -1e30f;
#pragma unroll
    for (int j = 0; j < 4; ++j) {
      mx0 = fmaxf(mx0, fmaxf(s[j][0], s[j][1]));
      mx1 = fmaxf(mx1, fmaxf(s[j][2], s[j][3]));
    }
    mx0 = fmaxf(mx0, __shfl_xor_sync(0xffffffffu, mx0, 1));
    mx0 = fmaxf(mx0, __shfl_xor_sync(0xffffffffu, mx0, 2));
    mx1 = fmaxf(mx1, __shfl_xor_sync(0xffffffffu, mx1, 1));
    mx1 = fmaxf(mx1, __shfl_xor_sync(0xffffffffu, mx1, 2));
    float nm0 = fmaxf(m0, mx0), nm1 = fmaxf(m1, mx1);
    float c0 = __expf(m0 - nm0), c1 = __expf(m1 - nm1);
    m0 = nm0; m1 = nm1;

    float rs0 = 0.f, rs1 = 0.f;
#pragma unroll
    for (int j = 0; j < 4; ++j) {
      float p00 = __expf(s[j][0] - m0);
      float p01 = __expf(s[j][1] - m0);
      float p10 = __expf(s[j][2] - m1);
      float p11 = __expf(s[j][3] - m1);
      rs0 += p00 + p01; rs1 += p10 + p11;
      psm[ qr      * 33 + j * 8 + 2 * t    ] = tf32f(p00);
      psm[ qr      * 33 + j * 8 + 2 * t + 1] = tf32f(p01);
      psm[(qr + 8) * 33 + j * 8 + 2 * t    ] = tf32f(p10);
      psm[(qr + 8) * 33 + j * 8 + 2 * t + 1] = tf32f(p11);
    }
    rs0 += __shfl_xor_sync(0xffffffffu, rs0, 1);
    rs0 += __shfl_xor_sync(0xffffffffu, rs0, 2);
    rs1 += __shfl_xor_sync(0xffffffffu, rs1, 1);
    rs1 += __shfl_xor_sync(0xffffffffu, rs1, 2);
    l0 = l0 * c0 + rs0;
    l1 = l1 * c1 + rs1;
#pragma unroll
    for (int j = 0; j < 8; ++j) { o[j][0] *= c0; o[j][1] *= c0; o[j][2] *= c1; o[j][3] *= c1; }
    __syncwarp();

    // O += P * V
#pragma unroll
    for (int kk = 0; kk < 4; ++kk) {
      uint32_t a[4];
      a[0] = __float_as_uint(psm[ qr      * 33 + kk * 8 + t]);
      a[1] = __float_as_uint(psm[(qr + 8) * 33 + kk * 8 + t]);
      a[2] = __float_as_uint(psm[ qr      * 33 + kk * 8 + t + 4]);
      a[3] = __float_as_uint(psm[(qr + 8) * 33 + kk * 8 + t + 4]);
#pragma unroll
      for (int j = 0; j < 8; ++j) {
        uint32_t b0 = __float_as_uint(vsm[(kk * 8 + t)     * 68 + j * 8 + qr]);
        uint32_t b1 = __float_as_uint(vsm[(kk * 8 + t + 4) * 68 + j * 8 + qr]);
        mma_tf32(o[j], a, b0, b1);
      }
    }
  }

  // epilogue: normalize, bounce through smem, apply forward frame transform, store
  __syncthreads();
  float il0 = 1.0f / l0, il1 = 1.0f / l1;
  float* osm = sm + warp * 1088;   // [16][68]
#pragma unroll
  for (int j = 0; j < 8; ++j) {
    osm[ qr      * 68 + j * 8 + 2 * t    ] = o[j][0] * il0;
    osm[ qr      * 68 + j * 8 + 2 * t + 1] = o[j][1] * il0;
    osm[(qr + 8) * 68 + j * 8 + 2 * t    ] = o[j][2] * il1;
    osm[(qr + 8) * 68 + j * 8 + 2 * t + 1] = o[j][3] * il1;
  }
  __syncwarp();

  const int r  = lane >> 1;
  const int hf = lane & 1;
  const int n  = row0 + r;
  const float* Mg = frames + ((size_t)b * NSEQ + n) * 16;
  float M[16];
#pragma unroll
  for (int i = 0; i < 16; ++i) M[i] = Mg[i];
  const float* xr = osm + r * 68;
  float* og = out + ((size_t)bh * NSEQ + n) * CDIM;

  if (hf == 0) {
#pragma unroll
    for (int c = 0; c < 16; c += 4) {
      float4 v = make_float4(xr[c], xr[c + 1], xr[c + 2], xr[c + 3]);
      *reinterpret_cast<float4*>(og + c) = v;
    }
#pragma unroll
    for (int g = 0; g < 4; ++g) {
      const int base = 16 + g * 4;
      float x0 = xr[base], x1 = xr[base + 1], x2 = xr[base + 2], x3 = xr[base + 3];
      float4 y;
      y.x = M[0]*x0  + M[1]*x1  + M[2]*x2  + M[3]*x3;
      y.y = M[4]*x0  + M[5]*x1  + M[6]*x2  + M[7]*x3;
      y.z = M[8]*x0  + M[9]*x1  + M[10]*x2 + M[11]*x3;
      y.w = M[12]*x0 + M[13]*x1 + M[14]*x2 + M[15]*x3;
      *reinterpret_cast<float4*>(og + base) = y;
    }
  } else {
#pragma unroll
    for (int g = 4; g < 12; ++g) {
      const int base = 16 + g * 4;
      float x0 = xr[base], x1 = xr[base + 1], x2 = xr[base + 2], x3 = xr[base + 3];
      float4 y;
      y.x = M[0]*x0  + M[1]*x1  + M[2]*x2  + M[3]*x3;
      y.y = M[4]*x0  + M[5]*x1  + M[6]*x2  + M[7]*x3;
      y.z = M[8]*x0  + M[9]*x1  + M[10]*x2 + M[11]*x3;
      y.w = M[12]*x0 + M[13]*x1 + M[14]*x2 + M[15]*x3;
      *reinterpret_cast<float4*>(og + base) = y;
    }
  }
}

// ---------------- launch ----------------
extern "C" void kernel_launch(void* const* d_in, const int* in_sizes, int n_in,
                              void* d_out, int out_size) {
  const float* q      = (const float*)d_in[0];
  const float* k      = (const float*)d_in[1];
  const float* v      = (const float*)d_in[2];
  const float* frames = (const float*)d_in[3];
  float* out = (float*)d_out;

  invert_kernel<<<(BATCH * NSEQ + 255) / 256, 256>>>(frames);
  transform_kernel<<<dim3(BATCH * HEADS * (NSEQ / 64), 3), 256>>>(q, k, v);
  attn_kernel<<<dim3(BATCH * HEADS, NSEQ / 128), 256>>>(frames, out);
}

// round 2
// speedup vs baseline: 1.1815x; 1.1815x over previous
#include <cuda_runtime.h>
#include <cstdint>

#define BATCH 8
#define HEADS 8
#define NSEQ  1024
#define CDIM  64

// ---------------- scratch (static device globals: no runtime allocation) ----------------
__device__ float g_q[BATCH*HEADS*NSEQ*CDIM];   // transformed, pre-scaled by 1/8
__device__ float g_k[BATCH*HEADS*NSEQ*CDIM];   // transformed with eta*inv*eta
__device__ float g_v[BATCH*HEADS*NSEQ*CDIM];   // transformed

// ---------------- helpers ----------------
__device__ __forceinline__ uint32_t tf32bits(float x) {
  uint32_t r;
  asm("cvt.rna.tf32.f32 %0, %1;" : "=r"(r) : "f"(x));
  return r;
}

__device__ __forceinline__ void mma_tf32(float* d, const uint32_t* a, uint32_t b0, uint32_t b1) {
  asm("mma.sync.aligned.m16n8k8.row.col.f32.tf32.tf32.f32 "
      "{%0,%1,%2,%3}, {%4,%5,%6,%7}, {%8,%9}, {%0,%1,%2,%3};\n"
      : "+f"(d[0]), "+f"(d[1]), "+f"(d[2]), "+f"(d[3])
      : "r"(a[0]), "r"(a[1]), "r"(a[2]), "r"(a[3]), "r"(b0), "r"(b1));
}

__device__ __forceinline__ void cp16(uint32_t dst, const void* src) {
  asm volatile("cp.async.cg.shared.global [%0], [%1], 16;\n" :: "r"(dst), "l"(src));
}
__device__ __forceinline__ void cp_commit() { asm volatile("cp.async.commit_group;\n"); }

// adjugate 4x4 inverse
__device__ __forceinline__ void inv4x4(const float* mm, float* outv) {
  float inv[16];
  inv[0]  =  mm[5]*mm[10]*mm[15] - mm[5]*mm[11]*mm[14] - mm[9]*mm[6]*mm[15] + mm[9]*mm[7]*mm[14] + mm[13]*mm[6]*mm[11] - mm[13]*mm[7]*mm[10];
  inv[4]  = -mm[4]*mm[10]*mm[15] + mm[4]*mm[11]*mm[14] + mm[8]*mm[6]*mm[15] - mm[8]*mm[7]*mm[14] - mm[12]*mm[6]*mm[11] + mm[12]*mm[7]*mm[10];
  inv[8]  =  mm[4]*mm[9]*mm[15]  - mm[4]*mm[11]*mm[13] - mm[8]*mm[5]*mm[15] + mm[8]*mm[7]*mm[13] + mm[12]*mm[5]*mm[11] - mm[12]*mm[7]*mm[9];
  inv[12] = -mm[4]*mm[9]*mm[14]  + mm[4]*mm[10]*mm[13] + mm[8]*mm[5]*mm[14] - mm[8]*mm[6]*mm[13] - mm[12]*mm[5]*mm[10] + mm[12]*mm[6]*mm[9];
  inv[1]  = -mm[1]*mm[10]*mm[15] + mm[1]*mm[11]*mm[14] + mm[9]*mm[2]*mm[15] - mm[9]*mm[3]*mm[14] - mm[13]*mm[2]*mm[11] + mm[13]*mm[3]*mm[10];
  inv[5]  =  mm[0]*mm[10]*mm[15] - mm[0]*mm[11]*mm[14] - mm[8]*mm[2]*mm[15] + mm[8]*mm[3]*mm[14] + mm[12]*mm[2]*mm[11] - mm[12]*mm[3]*mm[10];
  inv[9]  = -mm[0]*mm[9]*mm[15]  + mm[0]*mm[11]*mm[13] + mm[8]*mm[1]*mm[15] - mm[8]*mm[3]*mm[13] - mm[12]*mm[1]*mm[11] + mm[12]*mm[3]*mm[9];
  inv[13] =  mm[0]*mm[9]*mm[14]  - mm[0]*mm[10]*mm[13] - mm[8]*mm[1]*mm[14] + mm[8]*mm[2]*mm[13] + mm[12]*mm[1]*mm[10] - mm[12]*mm[2]*mm[9];
  inv[2]  =  mm[1]*mm[6]*mm[15]  - mm[1]*mm[7]*mm[14]  - mm[5]*mm[2]*mm[15] + mm[5]*mm[3]*mm[14] + mm[13]*mm[2]*mm[7]  - mm[13]*mm[3]*mm[6];
  inv[6]  = -mm[0]*mm[6]*mm[15]  + mm[0]*mm[7]*mm[14]  + mm[4]*mm[2]*mm[15] - mm[4]*mm[3]*mm[14] - mm[12]*mm[2]*mm[7]  + mm[12]*mm[3]*mm[6];
  inv[10] =  mm[0]*mm[5]*mm[15]  - mm[0]*mm[7]*mm[13]  - mm[4]*mm[1]*mm[15] + mm[4]*mm[3]*mm[13] + mm[12]*mm[1]*mm[7]  - mm[12]*mm[3]*mm[5];
  inv[14] = -mm[0]*mm[5]*mm[14]  + mm[0]*mm[6]*mm[13]  + mm[4]*mm[1]*mm[14] - mm[4]*mm[2]*mm[13] - mm[12]*mm[1]*mm[6]  + mm[12]*mm[2]*mm[5];
  inv[3]  = -mm[1]*mm[6]*mm[11]  + mm[1]*mm[7]*mm[10]  + mm[5]*mm[2]*mm[11] - mm[5]*mm[3]*mm[10] - mm[9]*mm[2]*mm[7]   + mm[9]*mm[3]*mm[6];
  inv[7]  =  mm[0]*mm[6]*mm[11]  - mm[0]*mm[7]*mm[10]  - mm[4]*mm[2]*mm[11] + mm[4]*mm[3]*mm[10] + mm[8]*mm[2]*mm[7]   - mm[8]*mm[3]*mm[6];
  inv[11] = -mm[0]*mm[5]*mm[11]  + mm[0]*mm[7]*mm[9]   + mm[4]*mm[1]*mm[11] - mm[4]*mm[3]*mm[9]  - mm[8]*mm[1]*mm[7]   + mm[8]*mm[3]*mm[5];
  inv[15] =  mm[0]*mm[5]*mm[10]  - mm[0]*mm[6]*mm[9]   - mm[4]*mm[1]*mm[10] + mm[4]*mm[2]*mm[9]  + mm[8]*mm[1]*mm[6]   - mm[8]*mm[2]*mm[5];
  float det = mm[0]*inv[0] + mm[1]*inv[4] + mm[2]*inv[8] + mm[3]*inv[12];
  float id = 1.0f / det;
#pragma unroll
  for (int j = 0; j < 16; ++j) outv[j] = inv[j] * id;
}

// ---------------- kernel 1: frame transform of q/k/v (inverse fused inline) ----------------
// grid.x = BH*16 (64 rows per block), grid.y = 3 (q,k,v). 256 threads: 4 per row.
__global__ void __launch_bounds__(256) transform_kernel(
    const float* __restrict__ qin, const float* __restrict__ kin,
    const float* __restrict__ vin, const float* __restrict__ frames) {
  const int kind = blockIdx.y;
  const int bh   = blockIdx.x >> 4;
  const int nblk = blockIdx.x & 15;
  const int b    = bh >> 3;
  const int tid  = threadIdx.x;
  const int row  = tid >> 2;
  const int part = tid & 3;
  const int n0   = nblk * 64;

  __shared__ float Msm[64 * 16];
  if (tid < 64) {
    float mm[16];
    const float* fp = frames + ((size_t)b * NSEQ + n0 + tid) * 16;
#pragma unroll
    for (int j = 0; j < 16; ++j) mm[j] = fp[j];
    inv4x4(mm, Msm + tid * 16);
  }
  __syncthreads();

  const float* x = (kind == 0 ? qin : kind == 1 ? kin : vin) + ((size_t)bh * NSEQ + n0) * CDIM;
  float*       y = (kind == 0 ? g_q : kind == 1 ? g_k : g_v) + ((size_t)bh * NSEQ + n0) * CDIM;
  const float scale = (kind == 0) ? 0.125f : 1.0f;   // fold 1/sqrt(C) into Q

  const float* xr = x + row * CDIM;
  float*       yr = y + row * CDIM;

  if (part == 0) {
#pragma unroll
    for (int c = 0; c < 16; c += 4) {
      float4 v = *reinterpret_cast<const float4*>(xr + c);
      v.x *= scale; v.y *= scale; v.z *= scale; v.w *= scale;
      *reinterpret_cast<float4*>(yr + c) = v;
    }
  } else {
    float M[16];
    const float* Mp = Msm + row * 16;
    if (kind == 1) {
#pragma unroll
      for (int i = 0; i < 4; ++i)
#pragma unroll
        for (int j = 0; j < 4; ++j) {
          float sgn = ((i == 0) == (j == 0)) ? 1.0f : -1.0f;  // eta*M*eta
          M[i * 4 + j] = Mp[i * 4 + j] * sgn;
        }
    } else {
#pragma unroll
      for (int i = 0; i < 16; ++i) M[i] = Mp[i] * scale;
    }
    const int base = 16 + (part - 1) * 16;
#pragma unroll
    for (int g = 0; g < 4; ++g) {
      float4 v = *reinterpret_cast<const float4*>(xr + base + g * 4);
      float4 o;
      o.x = M[0]*v.x  + M[1]*v.y  + M[2]*v.z  + M[3]*v.w;
      o.y = M[4]*v.x  + M[5]*v.y  + M[6]*v.z  + M[7]*v.w;
      o.z = M[8]*v.x  + M[9]*v.y  + M[10]*v.z + M[11]*v.w;
      o.w = M[12]*v.x + M[13]*v.y + M[14]*v.z + M[15]*v.w;
      *reinterpret_cast<float4*>(yr + base + g * 4) = o;
    }
  }
}

// ---------------- kernel 2: flash attention (tf32 mma, cp.async double-buffer) ----------------
// grid: (BH=64, 8 row-blocks of 128). 8 warps, 16 rows/warp. KV tile BN=32, 2 stages.
// Dynamic smem layout (floats):
//   stage s (s=0,1) at s*4352: K[32][68] then V[32][68]
//   P (per-warp [16][33]) at 8704 + warp*528
//   epilogue reuses [0, 8704)
__global__ void __launch_bounds__(256, 2) attn_kernel(const float* __restrict__ frames,
                                                      float* __restrict__ out) {
  extern __shared__ float sm[];

  const int bh   = blockIdx.x;
  const int mb   = blockIdx.y;
  const int b    = bh >> 3;
  const int tid  = threadIdx.x;
  const int warp = tid >> 5;
  const int lane = tid & 31;
  const int qr   = lane >> 2;   // row within 8-row group
  const int t    = lane & 3;    // col group
  const int row0 = mb * 128 + warp * 16;

  const float* Qg = g_q + (size_t)bh * NSEQ * CDIM;
  const float* Kg = g_k + (size_t)bh * NSEQ * CDIM;
  const float* Vg = g_v + (size_t)bh * NSEQ * CDIM;

  // Q fragments (16 x 64), tf32
  uint32_t qa[8][4];
#pragma unroll
  for (int kk = 0; kk < 8; ++kk) {
    const float* q0 = Qg + (size_t)(row0 + qr)     * CDIM + kk * 8;
    const float* q1 = Qg + (size_t)(row0 + qr + 8) * CDIM + kk * 8;
    qa[kk][0] = tf32bits(q0[t]);
    qa[kk][1] = tf32bits(q1[t]);
    qa[kk][2] = tf32bits(q0[t + 4]);
    qa[kk][3] = tf32bits(q1[t + 4]);
  }

  float o[8][4];
#pragma unroll
  for (int j = 0; j < 8; ++j) { o[j][0]=0.f; o[j][1]=0.f; o[j][2]=0.f; o[j][3]=0.f; }
  float m0 = -1e30f, m1 = -1e30f, l0 = 0.f, l1 = 0.f;

  float* psm = sm + 8704 + warp * 528;   // per-warp [16][33]
  const uint32_t smaddr = (uint32_t)__cvta_generic_to_shared(sm);

  // prefetch tile 0 into stage 0
  {
    const float4* Ksrc = reinterpret_cast<const float4*>(Kg);
    const float4* Vsrc = reinterpret_cast<const float4*>(Vg);
#pragma unroll
    for (int e0 = 0; e0 < 2; ++e0) {
      int e = tid + e0 * 256;
      int r = e >> 4, c = (e & 15) << 2;
      uint32_t off = smaddr + (uint32_t)(r * 68 + c) * 4u;
      cp16(off, Ksrc + e);
      cp16(off + 2176u * 4u, Vsrc + e);
    }
    cp_commit();
  }

  for (int tile = 0; tile < NSEQ / 32; ++tile) {
    const int cur = tile & 1;
    if (tile + 1 < NSEQ / 32) {
      const float4* Ksrc = reinterpret_cast<const float4*>(Kg + (size_t)(tile + 1) * 32 * CDIM);
      const float4* Vsrc = reinterpret_cast<const float4*>(Vg + (size_t)(tile + 1) * 32 * CDIM);
      uint32_t sbase = smaddr + (uint32_t)((cur ^ 1) * 4352) * 4u;
#pragma unroll
      for (int e0 = 0; e0 < 2; ++e0) {
        int e = tid + e0 * 256;
        int r = e >> 4, c = (e & 15) << 2;
        uint32_t off = sbase + (uint32_t)(r * 68 + c) * 4u;
        cp16(off, Ksrc + e);
        cp16(off + 2176u * 4u, Vsrc + e);
      }
      cp_commit();
      asm volatile("cp.async.wait_group 1;\n");
    } else {
      asm volatile("cp.async.wait_group 0;\n");
    }
    __syncthreads();

    const float* ksm = sm + cur * 4352;
    const float* vsm = ksm + 2176;

    // S = Q * K^T  (16 x 32)
    float s[4][4];
#pragma unroll
    for (int j = 0; j < 4; ++j) { s[j][0]=0.f; s[j][1]=0.f; s[j][2]=0.f; s[j][3]=0.f; }
#pragma unroll
    for (int kk = 0; kk < 8; ++kk) {
#pragma unroll
      for (int j = 0; j < 4; ++j) {
        uint32_t b0 = tf32bits(ksm[(j * 8 + qr) * 68 + kk * 8 + t]);
        uint32_t b1 = tf32bits(ksm[(j * 8 + qr) * 68 + kk * 8 + t + 4]);
        mma_tf32(s[j], qa[kk], b0, b1);
      }
    }

    // online softmax
    float mx0 = -1e30f, mx1 = -1e30f;
#pragma unroll
    for (int j = 0; j < 4; ++j) {
      mx0 = fmaxf(mx0, fmaxf(s[j][0], s[j][1]));
      mx1 = fmaxf(mx1, fmaxf(s[j][2], s[j][3]));
    }
    mx0 = fmaxf(mx0, __shfl_xor_sync(0xffffffffu, mx0, 1));
    mx0 = fmaxf(mx0, __shfl_xor_sync(0xffffffffu, mx0, 2));
    mx1 = fmaxf(mx1, __shfl_xor_sync(0xffffffffu, mx1, 1));
    mx1 = fmaxf(mx1, __shfl_xor_sync(0xffffffffu, mx1, 2));
    float nm0 = fmaxf(m0, mx0), nm1 = fmaxf(m1, mx1);
    float c0 = __expf(m0 - nm0), c1 = __expf(m1 - nm1);
    m0 = nm0; m1 = nm1;

    float rs0 = 0.f, rs1 = 0.f;
#pragma unroll
    for (int j = 0; j < 4; ++j) {
      float p00 = __expf(s[j][0] - m0);
      float p01 = __expf(s[j][1] - m0);
      float p10 = __expf(s[j][2] - m1);
      float p11 = __expf(s[j][3] - m1);
      rs0 += p00 + p01; rs1 += p10 + p11;
      psm[ qr      * 33 + j * 8 + 2 * t    ] = p00;
      psm[ qr      * 33 + j * 8 + 2 * t + 1] = p01;
      psm[(qr + 8) * 33 + j * 8 + 2 * t    ] = p10;
      psm[(qr + 8) * 33 + j * 8 + 2 * t + 1] = p11;
    }
    rs0 += __shfl_xor_sync(0xffffffffu, rs0, 1);
    rs0 += __shfl_xor_sync(0xffffffffu, rs0, 2);
    rs1 += __shfl_xor_sync(0xffffffffu, rs1, 1);
    rs1 += __shfl_xor_sync(0xffffffffu, rs1, 2);
    l0 = l0 * c0 + rs0;
    l1 = l1 * c1 + rs1;
#pragma unroll
    for (int j = 0; j < 8; ++j) { o[j][0] *= c0; o[j][1] *= c0; o[j][2] *= c1; o[j][3] *= c1; }
    __syncwarp();

    // O += P * V
#pragma unroll
    for (int kk = 0; kk < 4; ++kk) {
      uint32_t a[4];
      a[0] = tf32bits(psm[ qr      * 33 + kk * 8 + t]);
      a[1] = tf32bits(psm[(qr + 8) * 33 + kk * 8 + t]);
      a[2] = tf32bits(psm[ qr      * 33 + kk * 8 + t + 4]);
      a[3] = tf32bits(psm[(qr + 8) * 33 + kk * 8 + t + 4]);
#pragma unroll
      for (int j = 0; j < 8; ++j) {
        uint32_t b0 = tf32bits(vsm[(kk * 8 + t)     * 68 + j * 8 + qr]);
        uint32_t b1 = tf32bits(vsm[(kk * 8 + t + 4) * 68 + j * 8 + qr]);
        mma_tf32(o[j], a, b0, b1);
      }
    }
    __syncthreads();
  }

  // epilogue: normalize, bounce through smem, apply forward frame transform, store
  float il0 = 1.0f / l0, il1 = 1.0f / l1;
  float* osm = sm + warp * 1088;   // [16][68]
#pragma unroll
  for (int j = 0; j < 8; ++j) {
    osm[ qr      * 68 + j * 8 + 2 * t    ] = o[j][0] * il0;
    osm[ qr      * 68 + j * 8 + 2 * t + 1] = o[j][1] * il0;
    osm[(qr + 8) * 68 + j * 8 + 2 * t    ] = o[j][2] * il1;
    osm[(qr + 8) * 68 + j * 8 + 2 * t + 1] = o[j][3] * il1;
  }
  __syncwarp();

  const int r  = lane >> 1;
  const int hf = lane & 1;
  const int n  = row0 + r;
  const float* Mg = frames + ((size_t)b * NSEQ + n) * 16;
  float M[16];
#pragma unroll
  for (int i = 0; i < 16; ++i) M[i] = Mg[i];
  const float* xr = osm + r * 68;
  float* og = out + ((size_t)bh * NSEQ + n) * CDIM;

  if (hf == 0) {
#pragma unroll
    for (int c = 0; c < 16; c += 4) {
      float4 v = make_float4(xr[c], xr[c + 1], xr[c + 2], xr[c + 3]);
      *reinterpret_cast<float4*>(og + c) = v;
    }
#pragma unroll
    for (int g = 0; g < 4; ++g) {
      const int base = 16 + g * 4;
      float x0 = xr[base], x1 = xr[base + 1], x2 = xr[base + 2], x3 = xr[base + 3];
      float4 y;
      y.x = M[0]*x0  + M[1]*x1  + M[2]*x2  + M[3]*x3;
      y.y = M[4]*x0  + M[5]*x1  + M[6]*x2  + M[7]*x3;
      y.z = M[8]*x0  + M[9]*x1  + M[10]*x2 + M[11]*x3;
      y.w = M[12]*x0 + M[13]*x1 + M[14]*x2 + M[15]*x3;
      *reinterpret_cast<float4*>(og + base) = y;
    }
  } else {
#pragma unroll
    for (int g = 4; g < 12; ++g) {
      const int base = 16 + g * 4;
      float x0 = xr[base], x1 = xr[base + 1], x2 = xr[base + 2], x3 = xr[base + 3];
      float4 y;
      y.x = M[0]*x0  + M[1]*x1  + M[2]*x2  + M[3]*x3;
      y.y = M[4]*x0  + M[5]*x1  + M[6]*x2  + M[7]*x3;
      y.z = M[8]*x0  + M[9]*x1  + M[10]*x2 + M[11]*x3;
      y.w = M[12]*x0 + M[13]*x1 + M[14]*x2 + M[15]*x3;
      *reinterpret_cast<float4*>(og + base) = y;
    }
  }
}

// ---------------- launch ----------------
extern "C" void kernel_launch(void* const* d_in, const int* in_sizes, int n_in,
                              void* d_out, int out_size) {
  const float* q      = (const float*)d_in[0];
  const float* k      = (const float*)d_in[1];
  const float* v      = (const float*)d_in[2];
  const float* frames = (const float*)d_in[3];
  float* out = (float*)d_out;

  cudaFuncSetAttribute(attn_kernel, cudaFuncAttributeMaxDynamicSharedMemorySize, 51712);

  transform_kernel<<<dim3(BATCH * HEADS * (NSEQ / 64), 3), 256>>>(q, k, v, frames);
  attn_kernel<<<dim3(BATCH * HEADS, NSEQ / 128), 256, 51712>>>(frames, out);
}

// round 4
// speedup vs baseline: 2.7884x; 2.3600x over previous
#include <cuda_runtime.h>
#include <cuda_fp16.h>
#include <cstdint>

#define BATCH 8
#define HEADS 8
#define NSEQ  1024
#define CDIM  64
#define BHN   (BATCH*HEADS)
#define BN    64
#define NT    (NSEQ/BN)

// ---------------- scratch (static device globals) ----------------
__device__ __half g_q[BHN*NSEQ*CDIM];   // [bh][n][c] fp16, q pre-scaled by 1/8
__device__ __half g_k[BHN*NSEQ*CDIM];   // [bh][n][c] fp16, eta*inv*eta applied
__device__ __half g_v[BHN*NSEQ*CDIM];   // [bh][n][c] fp16

// ---------------- helpers ----------------
__device__ __forceinline__ uint32_t s2u(const void* p){
  uint32_t a; asm("{ .reg .u64 t; cvta.to.shared.u64 t, %1; cvt.u32.u64 %0, t; }" : "=r"(a) : "l"(p));
  return a;
}
#define SWZ(o) ((uint32_t)(o) ^ ((((uint32_t)(o))>>3)&0x70))

__device__ __forceinline__ void cp16(uint32_t dst, const void* src) {
  asm volatile("cp.async.cg.shared.global [%0], [%1], 16;\n" :: "r"(dst), "l"(src));
}
__device__ __forceinline__ void cp_commit() { asm volatile("cp.async.commit_group;\n"); }

__device__ __forceinline__ void ldsm4(uint32_t* r, uint32_t a){
  asm volatile("ldmatrix.sync.aligned.m8n8.x4.shared.b16 {%0,%1,%2,%3}, [%4];"
    : "=r"(r[0]),"=r"(r[1]),"=r"(r[2]),"=r"(r[3]) : "r"(a));
}
__device__ __forceinline__ void ldsm4t(uint32_t* r, uint32_t a){
  asm volatile("ldmatrix.sync.aligned.m8n8.x4.trans.shared.b16 {%0,%1,%2,%3}, [%4];"
    : "=r"(r[0]),"=r"(r[1]),"=r"(r[2]),"=r"(r[3]) : "r"(a));
}
__device__ __forceinline__ void mma16816(float* d, const uint32_t* a, uint32_t b0, uint32_t b1){
  asm volatile("mma.sync.aligned.m16n8k16.row.col.f32.f16.f16.f32 "
    "{%0,%1,%2,%3},{%4,%5,%6,%7},{%8,%9},{%0,%1,%2,%3};"
    : "+f"(d[0]),"+f"(d[1]),"+f"(d[2]),"+f"(d[3])
    : "r"(a[0]),"r"(a[1]),"r"(a[2]),"r"(a[3]),"r"(b0),"r"(b1));
}
__device__ __forceinline__ uint32_t packh2(float x, float y){
  __half2 h = __floats2half2_rn(x, y);
  return *reinterpret_cast<uint32_t*>(&h);
}

// adjugate 4x4 inverse
__device__ __forceinline__ void inv4x4(const float* mm, float* outv) {
  float inv[16];
  inv[0]  =  mm[5]*mm[10]*mm[15] - mm[5]*mm[11]*mm[14] - mm[9]*mm[6]*mm[15] + mm[9]*mm[7]*mm[14] + mm[13]*mm[6]*mm[11] - mm[13]*mm[7]*mm[10];
  inv[4]  = -mm[4]*mm[10]*mm[15] + mm[4]*mm[11]*mm[14] + mm[8]*mm[6]*mm[15] - mm[8]*mm[7]*mm[14] - mm[12]*mm[6]*mm[11] + mm[12]*mm[7]*mm[10];
  inv[8]  =  mm[4]*mm[9]*mm[15]  - mm[4]*mm[11]*mm[13] - mm[8]*mm[5]*mm[15] + mm[8]*mm[7]*mm[13] + mm[12]*mm[5]*mm[11] - mm[12]*mm[7]*mm[9];
  inv[12] = -mm[4]*mm[9]*mm[14]  + mm[4]*mm[10]*mm[13] + mm[8]*mm[5]*mm[14] - mm[8]*mm[6]*mm[13] - mm[12]*mm[5]*mm[10] + mm[12]*mm[6]*mm[9];
  inv[1]  = -mm[1]*mm[10]*mm[15] + mm[1]*mm[11]*mm[14] + mm[9]*mm[2]*mm[15] - mm[9]*mm[3]*mm[14] - mm[13]*mm[2]*mm[11] + mm[13]*mm[3]*mm[10];
  inv[5]  =  mm[0]*mm[10]*mm[15] - mm[0]*mm[11]*mm[14] - mm[8]*mm[2]*mm[15] + mm[8]*mm[3]*mm[14] + mm[12]*mm[2]*mm[11] - mm[12]*mm[3]*mm[10];
  inv[9]  = -mm[0]*mm[9]*mm[15]  + mm[0]*mm[11]*mm[13] + mm[8]*mm[1]*mm[15] - mm[8]*mm[3]*mm[13] - mm[12]*mm[1]*mm[11] + mm[12]*mm[3]*mm[9];
  inv[13] =  mm[0]*mm[9]*mm[14]  - mm[0]*mm[10]*mm[13] - mm[8]*mm[1]*mm[14] + mm[8]*mm[2]*mm[13] + mm[12]*mm[1]*mm[10] - mm[12]*mm[2]*mm[9];
  inv[2]  =  mm[1]*mm[6]*mm[15]  - mm[1]*mm[7]*mm[14]  - mm[5]*mm[2]*mm[15] + mm[5]*mm[3]*mm[14] + mm[13]*mm[2]*mm[7]  - mm[13]*mm[3]*mm[6];
  inv[6]  = -mm[0]*mm[6]*mm[15]  + mm[0]*mm[7]*mm[14]  + mm[4]*mm[2]*mm[15] - mm[4]*mm[3]*mm[14] - mm[12]*mm[2]*mm[7]  + mm[12]*mm[3]*mm[6];
  inv[10] =  mm[0]*mm[5]*mm[15]  - mm[0]*mm[7]*mm[13]  - mm[4]*mm[1]*mm[15] + mm[4]*mm[3]*mm[13] + mm[12]*mm[1]*mm[7]  - mm[12]*mm[3]*mm[5];
  inv[14] = -mm[0]*mm[5]*mm[14]  + mm[0]*mm[6]*mm[13]  + mm[4]*mm[1]*mm[14] - mm[4]*mm[2]*mm[13] - mm[12]*mm[1]*mm[6]  + mm[12]*mm[2]*mm[5];
  inv[3]  = -mm[1]*mm[6]*mm[11]  + mm[1]*mm[7]*mm[10]  + mm[5]*mm[2]*mm[11] - mm[5]*mm[3]*mm[10] - mm[9]*mm[2]*mm[7]   + mm[9]*mm[3]*mm[6];
  inv[7]  =  mm[0]*mm[6]*mm[11]  - mm[0]*mm[7]*mm[10]  - mm[4]*mm[2]*mm[11] + mm[4]*mm[3]*mm[10] + mm[8]*mm[2]*mm[7]   - mm[8]*mm[3]*mm[6];
  inv[11] = -mm[0]*mm[5]*mm[11]  + mm[0]*mm[7]*mm[9]   + mm[4]*mm[1]*mm[11] - mm[4]*mm[3]*mm[9]  - mm[8]*mm[1]*mm[7]   + mm[8]*mm[3]*mm[5];
  inv[15] =  mm[0]*mm[5]*mm[10]  - mm[0]*mm[6]*mm[9]   - mm[4]*mm[1]*mm[10] + mm[4]*mm[2]*mm[9]  + mm[8]*mm[1]*mm[6]   - mm[8]*mm[2]*mm[5];
  float det = mm[0]*inv[0] + mm[1]*inv[4] + mm[2]*inv[8] + mm[3]*inv[12];
  float id = 1.0f / det;
#pragma unroll
  for (int j = 0; j < 16; ++j) outv[j] = inv[j] * id;
}

// ---------------- kernel 1: frame transform -> fp16 ----------------
// grid.x = BH*16 (64 rows/block), grid.y = 3 (q,k,v). 256 threads: 4 per row.
__global__ void __launch_bounds__(256) transform_kernel(
    const float* __restrict__ qin, const float* __restrict__ kin,
    const float* __restrict__ vin, const float* __restrict__ frames) {
  const int kind = blockIdx.y;
  const int bh   = blockIdx.x >> 4;
  const int nblk = blockIdx.x & 15;
  const int b    = bh >> 3;
  const int tid  = threadIdx.x;
  const int row  = tid >> 2;
  const int part = tid & 3;
  const int n0   = nblk * 64;

  __shared__ float Msm[64 * 16];
  if (tid < 64) {
    float mm[16];
    const float* fp = frames + ((size_t)b * NSEQ + n0 + tid) * 16;
#pragma unroll
    for (int j = 0; j < 16; ++j) mm[j] = fp[j];
    inv4x4(mm, Msm + tid * 16);
  }
  __syncthreads();

  const float* x = (kind == 0 ? qin : kind == 1 ? kin : vin) + ((size_t)bh * NSEQ + n0) * CDIM;
  const float scale = (kind == 0) ? 0.125f : 1.0f;
  const float* xr = x + row * CDIM;
  const int n = n0 + row;

  float val[16];
  if (part == 0) {
#pragma unroll
    for (int j = 0; j < 16; ++j) val[j] = xr[j] * scale;
  } else {
    float M[16];
    const float* Mp = Msm + row * 16;
    if (kind == 1) {
#pragma unroll
      for (int i = 0; i < 4; ++i)
#pragma unroll
        for (int j = 0; j < 4; ++j) {
          float sgn = ((i == 0) == (j == 0)) ? 1.0f : -1.0f;  // eta*M*eta
          M[i * 4 + j] = Mp[i * 4 + j] * sgn;
        }
    } else {
#pragma unroll
      for (int i = 0; i < 16; ++i) M[i] = Mp[i] * scale;
    }
    const int base = 16 + (part - 1) * 16;
#pragma unroll
    for (int g = 0; g < 4; ++g) {
      float4 v = *reinterpret_cast<const float4*>(xr + base + g * 4);
      val[g*4+0] = M[0]*v.x  + M[1]*v.y  + M[2]*v.z  + M[3]*v.w;
      val[g*4+1] = M[4]*v.x  + M[5]*v.y  + M[6]*v.z  + M[7]*v.w;
      val[g*4+2] = M[8]*v.x  + M[9]*v.y  + M[10]*v.z + M[11]*v.w;
      val[g*4+3] = M[12]*v.x + M[13]*v.y + M[14]*v.z + M[15]*v.w;
    }
  }

  const int cbase = (part == 0) ? 0 : 16 + (part - 1) * 16;
  __half* yr = (kind == 0 ? g_q : kind == 1 ? g_k : g_v) + ((size_t)bh * NSEQ + n) * CDIM + cbase;
  uint32_t w[8];
#pragma unroll
  for (int j = 0; j < 8; ++j) w[j] = packh2(val[2*j], val[2*j+1]);
  uint4* dst = reinterpret_cast<uint4*>(yr);
  dst[0] = make_uint4(w[0], w[1], w[2], w[3]);
  dst[1] = make_uint4(w[4], w[5], w[6], w[7]);
}

// ---------------- kernel 2: fp16 flash attention (ldmatrix + m16n8k16) ----------------
// grid (BH=64, 8). 256 threads = 8 warps, 16 q-rows/warp, BM=128, BN=64, 2 stages.
// smem bytes: Q[128][64]h @0 (16KB, swizzled 128B rows),
//             K stages @16384/@24576 (8KB each), V stages @32768/@40960 (8KB each).
// Epilogue reuses [0, 34816) as per-warp [16][68] f32.
#define QOFF 0u
#define KOFF 16384u
#define VOFF 32768u
#define SMEM_BYTES 49152

__global__ void __launch_bounds__(256, 2) attn_kernel(const float* __restrict__ frames,
                                                      float* __restrict__ out) {
  extern __shared__ __align__(128) char smem[];
  const int bh   = blockIdx.x;
  const int mb   = blockIdx.y;
  const int b    = bh >> 3;
  const int tid  = threadIdx.x;
  const int warp = tid >> 5;
  const int lane = tid & 31;
  const int qr   = lane >> 2;   // 0..7
  const int t4   = lane & 3;    // 0..3
  const int i8   = lane & 7;
  const int g8   = lane >> 3;   // 0..3
  const uint32_t smaddr = s2u(smem);

  const __half* Qg = g_q + ((size_t)bh * NSEQ + mb * 128) * CDIM;
  const __half* Kg = g_k + (size_t)bh * NSEQ * CDIM;
  const __half* Vg = g_v + (size_t)bh * NSEQ * CDIM;

  // prologue: Q (128 rows) + KV tile 0, one cp.async group
#pragma unroll
  for (int i = 0; i < 4; ++i) {
    int ch = tid + i * 256; int r = ch >> 3, c = ch & 7;
    cp16(smaddr + QOFF + SWZ(r * 128 + c * 16), Qg + r * CDIM + c * 8);
  }
#pragma unroll
  for (int i = 0; i < 2; ++i) {
    int ch = tid + i * 256; int r = ch >> 3, c = ch & 7;
    cp16(smaddr + KOFF + SWZ(r * 128 + c * 16), Kg + r * CDIM + c * 8);
    cp16(smaddr + VOFF + SWZ(r * 128 + c * 16), Vg + r * CDIM + c * 8);
  }
  cp_commit();

  float o[8][4];
#pragma unroll
  for (int j = 0; j < 8; ++j) { o[j][0]=0.f; o[j][1]=0.f; o[j][2]=0.f; o[j][3]=0.f; }
  float m0 = -1e30f, m1 = -1e30f, l0 = 0.f, l1 = 0.f;
  uint32_t qa[4][4];

  // lane-dependent ldmatrix address components
  const uint32_t q_row = (uint32_t)(warp * 16 + i8 + ((g8 & 1) << 3));   // A-layout
  const uint32_t q_cad = (uint32_t)((g8 >> 1) << 4);
  const uint32_t k_rad = (uint32_t)(((g8 >> 1) << 3) + i8);             // B non-trans
  const uint32_t k_cad = (uint32_t)((g8 & 1) << 4);
  const uint32_t v_rad = (uint32_t)(((g8 & 1) << 3) + i8);              // B trans
  const uint32_t v_cad = (uint32_t)((g8 >> 1) << 4);

  for (int t = 0; t < NT; ++t) {
    const uint32_t cur = t & 1;
    if (t + 1 < NT) {
      const __half* Kn = Kg + (size_t)(t + 1) * BN * CDIM;
      const __half* Vn = Vg + (size_t)(t + 1) * BN * CDIM;
      const uint32_t kb = smaddr + KOFF + (cur ^ 1) * 8192;
      const uint32_t vb = smaddr + VOFF + (cur ^ 1) * 8192;
#pragma unroll
      for (int i = 0; i < 2; ++i) {
        int ch = tid + i * 256; int r = ch >> 3, c = ch & 7;
        cp16(kb + SWZ(r * 128 + c * 16), Kn + r * CDIM + c * 8);
        cp16(vb + SWZ(r * 128 + c * 16), Vn + r * CDIM + c * 8);
      }
      cp_commit();
      asm volatile("cp.async.wait_group 1;\n");
    } else {
      asm volatile("cp.async.wait_group 0;\n");
    }
    __syncthreads();

    if (t == 0) {
      // load Q fragments once (A-layout, 4 k16 tiles)
#pragma unroll
      for (int kk = 0; kk < 4; ++kk)
        ldsm4(qa[kk], smaddr + QOFF + SWZ(q_row * 128 + kk * 32 + q_cad));
    }

    const uint32_t kbase = smaddr + KOFF + cur * 8192;
    const uint32_t vbase = smaddr + VOFF + cur * 8192;

    // ---- S = Q * K^T (16 x 64) ----
    float s[8][4];
#pragma unroll
    for (int j = 0; j < 8; ++j) { s[j][0]=0.f; s[j][1]=0.f; s[j][2]=0.f; s[j][3]=0.f; }
#pragma unroll
    for (int kk = 0; kk < 4; ++kk) {
#pragma unroll
      for (int jp = 0; jp < 4; ++jp) {
        uint32_t r[4];
        ldsm4(r, kbase + SWZ((jp * 16 + k_rad) * 128 + kk * 32 + k_cad));
        mma16816(s[2*jp],   qa[kk], r[0], r[1]);
        mma16816(s[2*jp+1], qa[kk], r[2], r[3]);
      }
    }

    // ---- online softmax (rows qr / qr+8, reduce over t4 lanes) ----
    float mx0 = -1e30f, mx1 = -1e30f;
#pragma unroll
    for (int j = 0; j < 8; ++j) {
      mx0 = fmaxf(mx0, fmaxf(s[j][0], s[j][1]));
      mx1 = fmaxf(mx1, fmaxf(s[j][2], s[j][3]));
    }
    mx0 = fmaxf(mx0, __shfl_xor_sync(0xffffffffu, mx0, 1));
    mx0 = fmaxf(mx0, __shfl_xor_sync(0xffffffffu, mx0, 2));
    mx1 = fmaxf(mx1, __shfl_xor_sync(0xffffffffu, mx1, 1));
    mx1 = fmaxf(mx1, __shfl_xor_sync(0xffffffffu, mx1, 2));
    float nm0 = fmaxf(m0, mx0), nm1 = fmaxf(m1, mx1);
    float c0 = __expf(m0 - nm0), c1 = __expf(m1 - nm1);
    m0 = nm0; m1 = nm1;

    float rs0 = 0.f, rs1 = 0.f;
#pragma unroll
    for (int j = 0; j < 8; ++j) {
      s[j][0] = __expf(s[j][0] - m0);
      s[j][1] = __expf(s[j][1] - m0);
      s[j][2] = __expf(s[j][2] - m1);
      s[j][3] = __expf(s[j][3] - m1);
      rs0 += s[j][0] + s[j][1];
      rs1 += s[j][2] + s[j][3];
    }
    rs0 += __shfl_xor_sync(0xffffffffu, rs0, 1);
    rs0 += __shfl_xor_sync(0xffffffffu, rs0, 2);
    rs1 += __shfl_xor_sync(0xffffffffu, rs1, 1);
    rs1 += __shfl_xor_sync(0xffffffffu, rs1, 2);
    l0 = l0 * c0 + rs0;
    l1 = l1 * c1 + rs1;
#pragma unroll
    for (int j = 0; j < 8; ++j) { o[j][0] *= c0; o[j][1] *= c0; o[j][2] *= c1; o[j][3] *= c1; }

    // ---- O += P * V (P fragments packed from S fragments in registers) ----
#pragma unroll
    for (int kk = 0; kk < 4; ++kk) {
      uint32_t pa[4];
      pa[0] = packh2(s[2*kk][0],   s[2*kk][1]);
      pa[1] = packh2(s[2*kk][2],   s[2*kk][3]);
      pa[2] = packh2(s[2*kk+1][0], s[2*kk+1][1]);
      pa[3] = packh2(s[2*kk+1][2], s[2*kk+1][3]);
#pragma unroll
      for (int jp = 0; jp < 4; ++jp) {
        uint32_t r[4];
        ldsm4t(r, vbase + SWZ((kk * 16 + v_rad) * 128 + jp * 32 + v_cad));
        mma16816(o[2*jp],   pa, r[0], r[1]);
        mma16816(o[2*jp+1], pa, r[2], r[3]);
      }
    }
    __syncthreads();   // all smem reads of this stage done before it is refilled
  }

  // ---- epilogue: normalize, bounce through smem, forward frame transform ----
  float il0 = 1.0f / l0, il1 = 1.0f / l1;
  float* osm = reinterpret_cast<float*>(smem) + warp * 1088;   // [16][68]
#pragma unroll
  for (int j = 0; j < 8; ++j) {
    osm[ qr      * 68 + j * 8 + 2 * t4    ] = o[j][0] * il0;
    osm[ qr      * 68 + j * 8 + 2 * t4 + 1] = o[j][1] * il0;
    osm[(qr + 8) * 68 + j * 8 + 2 * t4    ] = o[j][2] * il1;
    osm[(qr + 8) * 68 + j * 8 + 2 * t4 + 1] = o[j][3] * il1;
  }
  __syncwarp();

  const int r  = lane >> 1;
  const int hf = lane & 1;
  const int n  = mb * 128 + warp * 16 + r;
  const float* Mg = frames + ((size_t)b * NSEQ + n) * 16;
  float M[16];
#pragma unroll
  for (int i = 0; i < 16; ++i) M[i] = Mg[i];
  const float* xr = osm + r * 68;
  float* og = out + ((size_t)bh * NSEQ + n) * CDIM;

  if (hf == 0) {
#pragma unroll
    for (int c = 0; c < 16; c += 4)
      *reinterpret_cast<float4*>(og + c) = make_float4(xr[c], xr[c+1], xr[c+2], xr[c+3]);
#pragma unroll
    for (int g = 0; g < 4; ++g) {
      const int base = 16 + g * 4;
      float x0 = xr[base], x1 = xr[base+1], x2 = xr[base+2], x3 = xr[base+3];
      float4 y;
      y.x = M[0]*x0  + M[1]*x1  + M[2]*x2  + M[3]*x3;
      y.y = M[4]*x0  + M[5]*x1  + M[6]*x2  + M[7]*x3;
      y.z = M[8]*x0  + M[9]*x1  + M[10]*x2 + M[11]*x3;
      y.w = M[12]*x0 + M[13]*x1 + M[14]*x2 + M[15]*x3;
      *reinterpret_cast<float4*>(og + base) = y;
    }
  } else {
#pragma unroll
    for (int g = 4; g < 12; ++g) {
      const int base = 16 + g * 4;
      float x0 = xr[base], x1 = xr[base+1], x2 = xr[base+2], x3 = xr[base+3];
      float4 y;
      y.x = M[0]*x0  + M[1]*x1  + M[2]*x2  + M[3]*x3;
      y.y = M[4]*x0  + M[5]*x1  + M[6]*x2  + M[7]*x3;
      y.z = M[8]*x0  + M[9]*x1  + M[10]*x2 + M[11]*x3;
      y.w = M[12]*x0 + M[13]*x1 + M[14]*x2 + M[15]*x3;
      *reinterpret_cast<float4*>(og + base) = y;
    }
  }
}

// ---------------- launch ----------------
extern "C" void kernel_launch(void* const* d_in, const int* in_sizes, int n_in,
                              void* d_out, int out_size) {
  const float* q      = (const float*)d_in[0];
  const float* k      = (const float*)d_in[1];
  const float* v      = (const float*)d_in[2];
  const float* frames = (const float*)d_in[3];
  float* out = (float*)d_out;

  cudaFuncSetAttribute(attn_kernel, cudaFuncAttributeMaxDynamicSharedMemorySize, SMEM_BYTES);

  transform_kernel<<<dim3(BHN * (NSEQ / 64), 3), 256>>>(q, k, v, frames);
  attn_kernel<<<dim3(BHN, NSEQ / 128), 256, SMEM_BYTES>>>(frames, out);
}